// round 9
// baseline (speedup 1.0000x reference)
#include <cuda_runtime.h>
#include <math.h>

#define T_TOK 1024
#define E_EXP 16
#define K_TOP 4
#define H_DIM 2048
#define I_DIM 2048
#define CAP   512
#define N1    (2*I_DIM)   /* 4096 */

// ---------------- scratch (device globals; no runtime allocation) ----------------
__device__ int   g_w1p[E_EXP*(H_DIM/4)*N1];     // [E][K/4][2I] int32: byte j = k = 4*k4+j
__device__ int   g_w2p[E_EXP*(I_DIM/4)*H_DIM];  // [E][K/4][H]
__device__ int   g_xq[T_TOK*(H_DIM/4)];         // packed int8 tokens [T][512]
__device__ float g_xs[T_TOK];
__device__ int   g_topk_i[T_TOK*K_TOP];
__device__ float g_topk_w[T_TOK*K_TOP];
__device__ int   g_rowsrc[E_EXP*CAP];
__device__ int   g_slot[T_TOK*K_TOP];
__device__ int   g_cnt[E_EXP];
__device__ float g_act[(size_t)E_EXP*CAP*I_DIM];   // swiglu output
__device__ int   g_hq[E_EXP*CAP*(I_DIM/4)];        // requantized act
__device__ float g_hs[E_EXP*CAP];
__device__ float g_z[(size_t)E_EXP*CAP*H_DIM];     // GEMM2 output

// ---------------- helpers ----------------
__device__ __forceinline__ int packb(float a, float b, float c, float d) {
    return ( __float2int_rn(a) & 0xff)
         | ((__float2int_rn(b) & 0xff) << 8)
         | ((__float2int_rn(c) & 0xff) << 16)
         | ((__float2int_rn(d) & 0xff) << 24);
}
__device__ __forceinline__ int q8c(float v, float s) {
    int q = __float2int_rn(v / s);
    q = max(-127, min(127, q));
    return q & 0xff;
}
// IMMA m16n8k32 s8*s8+s32
__device__ __forceinline__ void mma_s8(int* c, const int* a, const int* b) {
    asm volatile("mma.sync.aligned.m16n8k32.row.col.s32.s8.s8.s32 "
        "{%0,%1,%2,%3}, {%4,%5,%6,%7}, {%8,%9}, {%0,%1,%2,%3};"
        : "+r"(c[0]), "+r"(c[1]), "+r"(c[2]), "+r"(c[3])
        : "r"(a[0]), "r"(a[1]), "r"(a[2]), "r"(a[3]), "r"(b[0]), "r"(b[1]));
}

// ---------------- weight repack: f32 (int values) -> K-packed int8 ----------------
__global__ void k_pack(const float* __restrict__ in, int which, int Kd, int Nd) {
    int* __restrict__ out = which ? g_w2p : g_w1p;
    long long i4  = (long long)blockIdx.x * blockDim.x + threadIdx.x;
    long long lin = i4 * 4;
    long long perE = (long long)(Kd >> 2) * Nd;
    int e  = (int)(lin / perE);
    long long rem = lin - (long long)e * perE;
    int k4 = (int)(rem / Nd);
    int n  = (int)(rem - (long long)k4 * Nd);
    const float* p = in + ((long long)e * Kd + 4 * k4) * Nd + n;
    float4 r0 = *(const float4*)(p);
    float4 r1 = *(const float4*)(p + Nd);
    float4 r2 = *(const float4*)(p + 2 * Nd);
    float4 r3 = *(const float4*)(p + 3 * Nd);
    int4 o;
    o.x = packb(r0.x, r1.x, r2.x, r3.x);
    o.y = packb(r0.y, r1.y, r2.y, r3.y);
    o.z = packb(r0.z, r1.z, r2.z, r3.z);
    o.w = packb(r0.w, r1.w, r2.w, r3.w);
    *(int4*)(out + lin) = o;
}

// ---------------- gating: softmax + top-4 + renormalize ----------------
__global__ void k_gate(const float* __restrict__ logits) {
    int t = blockIdx.x, lane = threadIdx.x;
    float v = (lane < E_EXP) ? logits[t * E_EXP + lane] : -1e30f;
    float m = v;
    #pragma unroll
    for (int o = 16; o; o >>= 1) m = fmaxf(m, __shfl_xor_sync(0xffffffffu, m, o));
    float cur = (lane < E_EXP) ? expf(v - m) : -1.0f;
    float w[K_TOP]; int id[K_TOP];
    #pragma unroll
    for (int k = 0; k < K_TOP; k++) {
        float bv = cur; int bi = lane;
        #pragma unroll
        for (int o = 16; o; o >>= 1) {
            float ov = __shfl_xor_sync(0xffffffffu, bv, o);
            int   oi = __shfl_xor_sync(0xffffffffu, bi, o);
            if (ov > bv || (ov == bv && oi < bi)) { bv = ov; bi = oi; }
        }
        w[k] = bv; id[k] = bi;
        if (lane == bi) cur = -1.0f;
    }
    float s = w[0] + w[1] + w[2] + w[3];
    if (lane < K_TOP) {
        g_topk_i[t * K_TOP + lane] = id[lane];
        g_topk_w[t * K_TOP + lane] = w[lane] / s;
    }
}

// ---------------- per-row dynamic int8 quant ----------------
__global__ void k_quant(const float* __restrict__ xin, int which) {
    const float* x; int* q; float* s;
    if (which == 0) { x = xin;  q = g_xq; s = g_xs; }
    else            { x = g_act; q = g_hq; s = g_hs; }
    int r = blockIdx.x, t = threadIdx.x;
    const float* row = x + (long long)r * 2048;
    float4 a = *(const float4*)(row + t * 8);
    float4 b = *(const float4*)(row + t * 8 + 4);
    float mx = fmaxf(fmaxf(fmaxf(fabsf(a.x), fabsf(a.y)), fmaxf(fabsf(a.z), fabsf(a.w))),
                     fmaxf(fmaxf(fabsf(b.x), fabsf(b.y)), fmaxf(fabsf(b.z), fabsf(b.w))));
    __shared__ float sm[256];
    sm[t] = mx; __syncthreads();
    #pragma unroll
    for (int o = 128; o; o >>= 1) { if (t < o) sm[t] = fmaxf(sm[t], sm[t + o]); __syncthreads(); }
    float scale = fmaxf(sm[0] / 127.0f, 1e-8f);
    int2 o2;
    o2.x = q8c(a.x, scale) | (q8c(a.y, scale) << 8) | (q8c(a.z, scale) << 16) | (q8c(a.w, scale) << 24);
    o2.y = q8c(b.x, scale) | (q8c(b.y, scale) << 8) | (q8c(b.z, scale) << 16) | (q8c(b.w, scale) << 24);
    *(int2*)(q + (long long)r * 512 + t * 2) = o2;
    if (t == 0) s[r] = scale;
}

// ---------------- routing ----------------
__global__ void k_route() {
    int w = threadIdx.x >> 5, lane = threadIdx.x & 31;
    int base = 0;
    for (int c = 0; c < (T_TOK * K_TOP) / 32; c++) {
        int i = c * 32 + lane;
        int e = g_topk_i[i];
        unsigned mask = __ballot_sync(0xffffffffu, e == w);
        if (e == w) {
            int pos = base + __popc(mask & ((1u << lane) - 1u));
            if (pos < CAP) { g_rowsrc[w * CAP + pos] = i >> 2; g_slot[i] = w * CAP + pos; }
            else           { g_slot[i] = -1; }
        }
        base += __popc(mask);
    }
    int cnt = min(base, CAP);
    if (lane == 0) g_cnt[w] = cnt;
    for (int p = cnt + lane; p < CAP; p += 32) g_rowsrc[w * CAP + p] = -1;
}

// ---------------- GEMM1: IMMA m16n8k32, CTA 128m x (64 gate + 64 up), K=2048 ----------------
// grid (32, 4, 16). 8 warps = 4m x 2n; warp tile 32m x 32n (gate) + 32m x 32n (up).
__global__ void __launch_bounds__(256) k_gemm1(const float* __restrict__ w1s,
                                               const float* __restrict__ w1b,
                                               const float* __restrict__ smooth) {
    int e = blockIdx.z, mt = blockIdx.y, ng = blockIdx.x;
    int cnt = g_cnt[e];
    if (mt * 128 >= cnt) return;

    __shared__ int As[2][8 * 136];     // [k4][m], stride 136
    __shared__ int Bs[2][8 * 136];     // [k4][cc 0..127], stride 136 (cc<64 gate, >=64 up)
    __shared__ int s_src[128];
    __shared__ float s_xs[128];
    __shared__ float s_gs[64], s_gb[64], s_us[64], s_ub[64], s_sm[64];

    int t = threadIdx.x;
    if (t < 128) {
        int s = g_rowsrc[e * CAP + mt * 128 + t];
        s_src[t] = s;
        s_xs[t] = (s >= 0) ? g_xs[s] : 0.0f;
    }
    if (t < 64) {
        int n = ng * 64 + t;
        s_gs[t] = w1s[e * N1 + n];
        s_gb[t] = w1b[e * N1 + n];
        s_us[t] = w1s[e * N1 + I_DIM + n];
        s_ub[t] = w1b[e * N1 + I_DIM + n];
        s_sm[t] = smooth[e * I_DIM + n];
    }
    __syncthreads();

    int lane = t & 31, wid = t >> 5;
    int wm = (wid & 3) * 32;           // warp m offset
    int wn = (wid >> 2) * 32;          // warp n offset within 64 gate cols
    int grp = lane >> 2, qid = lane & 3;

    // staging indices
    int am = t >> 1, ajj = (t & 1) * 4;                    // A: 2 threads/row, int4 each
    int bj = t >> 5, bn4 = t & 31;                         // B: warp per k4 row
    int srcm = s_src[am];
    int bcc = bn4 * 4;
    long long bcol = (bcc < 64) ? (long long)(ng * 64 + bcc)
                                : (long long)(I_DIM + ng * 64 + (bcc - 64));
    const int* bptr = g_w1p + (long long)e * 512 * N1 + bcol;
    const int* aptr = (srcm >= 0) ? (g_xq + srcm * 512 + ajj) : (const int*)0;

    int accg[2][4][4], accu[2][4][4];
    #pragma unroll
    for (int i = 0; i < 2; i++)
        #pragma unroll
        for (int j = 0; j < 4; j++)
            #pragma unroll
            for (int k = 0; k < 4; k++) { accg[i][j][k] = 0; accu[i][j][k] = 0; }

    // prologue: stage chunk 0 into buf 0
    {
        int4 av = aptr ? *(const int4*)(aptr) : make_int4(0, 0, 0, 0);
        As[0][(ajj + 0) * 136 + am] = av.x;
        As[0][(ajj + 1) * 136 + am] = av.y;
        As[0][(ajj + 2) * 136 + am] = av.z;
        As[0][(ajj + 3) * 136 + am] = av.w;
        int4 bv = *(const int4*)(bptr + (long long)bj * N1);
        *(int4*)&Bs[0][bj * 136 + bn4 * 4] = bv;
    }
    __syncthreads();

    for (int kt = 0; kt < 64; kt++) {
        int buf = kt & 1;
        if (kt + 1 < 64) {
            int k4b = (kt + 1) * 8;
            int nb = buf ^ 1;
            int4 av = aptr ? *(const int4*)(aptr + k4b) : make_int4(0, 0, 0, 0);
            As[nb][(ajj + 0) * 136 + am] = av.x;
            As[nb][(ajj + 1) * 136 + am] = av.y;
            As[nb][(ajj + 2) * 136 + am] = av.z;
            As[nb][(ajj + 3) * 136 + am] = av.w;
            int4 bv = *(const int4*)(bptr + (long long)(k4b + bj) * N1);
            *(int4*)&Bs[nb][bj * 136 + bn4 * 4] = bv;
        }
        int a[2][4];
        #pragma unroll
        for (int mf = 0; mf < 2; mf++) {
            int mr = wm + mf * 16 + grp;
            a[mf][0] = As[buf][qid * 136 + mr];
            a[mf][1] = As[buf][qid * 136 + mr + 8];
            a[mf][2] = As[buf][(qid + 4) * 136 + mr];
            a[mf][3] = As[buf][(qid + 4) * 136 + mr + 8];
        }
        #pragma unroll
        for (int nf = 0; nf < 4; nf++) {
            int cc = wn + nf * 8 + grp;
            int bg[2] = { Bs[buf][qid * 136 + cc], Bs[buf][(qid + 4) * 136 + cc] };
            int bu[2] = { Bs[buf][qid * 136 + 64 + cc], Bs[buf][(qid + 4) * 136 + 64 + cc] };
            #pragma unroll
            for (int mf = 0; mf < 2; mf++) {
                mma_s8(accg[mf][nf], a[mf], bg);
                mma_s8(accu[mf][nf], a[mf], bu);
            }
        }
        __syncthreads();
    }

    // epilogue: dequant + swiglu, write g_act (cols ng*64 .. +64)
    #pragma unroll
    for (int mf = 0; mf < 2; mf++) {
        int r0 = wm + mf * 16 + grp;
        int r1 = r0 + 8;
        float xs0 = s_xs[r0], xs1 = s_xs[r1];
        float* d0 = g_act + ((size_t)e * CAP + mt * 128 + r0) * I_DIM + (size_t)ng * 64;
        float* d1 = g_act + ((size_t)e * CAP + mt * 128 + r1) * I_DIM + (size_t)ng * 64;
        #pragma unroll
        for (int nf = 0; nf < 4; nf++) {
            int nl = wn + nf * 8 + qid * 2;
            #pragma unroll
            for (int c = 0; c < 2; c++) {
                int n = nl + c;
                float gs = s_gs[n], gbv = s_gb[n], us = s_us[n], ubv = s_ub[n], smv = s_sm[n];
                // row r0: acc idx c, row r1: acc idx c+2
                float yg0 = (float)accg[mf][nf][c]     * xs0 * gs + gbv;
                float yu0 = (float)accu[mf][nf][c]     * xs0 * us + ubv;
                float yg1 = (float)accg[mf][nf][c + 2] * xs1 * gs + gbv;
                float yu1 = (float)accu[mf][nf][c + 2] * xs1 * us + ubv;
                float gg0 = fminf(yg0, 7.0f), uu0 = fminf(fmaxf(yu0, -7.0f), 7.0f);
                float gg1 = fminf(yg1, 7.0f), uu1 = fminf(fmaxf(yu1, -7.0f), 7.0f);
                d0[n] = gg0 / (1.0f + expf(-1.702f * gg0)) * (uu0 + 1.0f) * smv;
                d1[n] = gg1 / (1.0f + expf(-1.702f * gg1)) * (uu1 + 1.0f) * smv;
            }
        }
    }
}

// ---------------- GEMM2: IMMA m16n8k32, CTA 128m x 128n, K=2048 ----------------
// grid (16, 4, 16). 8 warps = 4m x 2n; warp tile 32m x 64n.
__global__ void __launch_bounds__(256) k_gemm2(const float* __restrict__ w2s,
                                               const float* __restrict__ w2b) {
    int e = blockIdx.z, mt = blockIdx.y, nt = blockIdx.x;
    int cnt = g_cnt[e];
    if (mt * 128 >= cnt) return;

    __shared__ int As[2][8 * 136];
    __shared__ int Bs[2][8 * 136];
    __shared__ float s_hs[128];
    __shared__ float s_zs[128], s_zb[128];

    int t = threadIdx.x;
    if (t < 128) {
        s_hs[t] = g_hs[e * CAP + mt * 128 + t];
        int n = nt * 128 + t;
        s_zs[t] = w2s[e * H_DIM + n];
        s_zb[t] = w2b[e * H_DIM + n];
    }
    __syncthreads();

    int lane = t & 31, wid = t >> 5;
    int wm = (wid & 3) * 32;
    int wn = (wid >> 2) * 64;
    int grp = lane >> 2, qid = lane & 3;

    int am = t >> 1, ajj = (t & 1) * 4;
    int bj = t >> 5, bn4 = t & 31;
    const int* aptr = g_hq + ((long long)e * CAP + mt * 128 + am) * 512 + ajj;
    const int* bptr = g_w2p + (long long)e * 512 * H_DIM + nt * 128 + bn4 * 4;

    int acc[2][8][4];
    #pragma unroll
    for (int i = 0; i < 2; i++)
        #pragma unroll
        for (int j = 0; j < 8; j++)
            #pragma unroll
            for (int k = 0; k < 4; k++) acc[i][j][k] = 0;

    {
        int4 av = *(const int4*)(aptr);
        As[0][(ajj + 0) * 136 + am] = av.x;
        As[0][(ajj + 1) * 136 + am] = av.y;
        As[0][(ajj + 2) * 136 + am] = av.z;
        As[0][(ajj + 3) * 136 + am] = av.w;
        int4 bv = *(const int4*)(bptr + (long long)bj * H_DIM);
        *(int4*)&Bs[0][bj * 136 + bn4 * 4] = bv;
    }
    __syncthreads();

    for (int kt = 0; kt < 64; kt++) {
        int buf = kt & 1;
        if (kt + 1 < 64) {
            int k4b = (kt + 1) * 8;
            int nb = buf ^ 1;
            int4 av = *(const int4*)(aptr + k4b);
            As[nb][(ajj + 0) * 136 + am] = av.x;
            As[nb][(ajj + 1) * 136 + am] = av.y;
            As[nb][(ajj + 2) * 136 + am] = av.z;
            As[nb][(ajj + 3) * 136 + am] = av.w;
            int4 bv = *(const int4*)(bptr + (long long)(k4b + bj) * H_DIM);
            *(int4*)&Bs[nb][bj * 136 + bn4 * 4] = bv;
        }
        int a[2][4];
        #pragma unroll
        for (int mf = 0; mf < 2; mf++) {
            int mr = wm + mf * 16 + grp;
            a[mf][0] = As[buf][qid * 136 + mr];
            a[mf][1] = As[buf][qid * 136 + mr + 8];
            a[mf][2] = As[buf][(qid + 4) * 136 + mr];
            a[mf][3] = As[buf][(qid + 4) * 136 + mr + 8];
        }
        #pragma unroll
        for (int nf = 0; nf < 8; nf++) {
            int cc = wn + nf * 8 + grp;
            int b[2] = { Bs[buf][qid * 136 + cc], Bs[buf][(qid + 4) * 136 + cc] };
            #pragma unroll
            for (int mf = 0; mf < 2; mf++)
                mma_s8(acc[mf][nf], a[mf], b);
        }
        __syncthreads();
    }

    #pragma unroll
    for (int mf = 0; mf < 2; mf++) {
        int r0 = wm + mf * 16 + grp;
        int r1 = r0 + 8;
        float hs0 = s_hs[r0], hs1 = s_hs[r1];
        float* d0 = g_z + ((size_t)e * CAP + mt * 128 + r0) * H_DIM + (size_t)nt * 128;
        float* d1 = g_z + ((size_t)e * CAP + mt * 128 + r1) * H_DIM + (size_t)nt * 128;
        #pragma unroll
        for (int nf = 0; nf < 8; nf++) {
            int nl = wn + nf * 8 + qid * 2;
            #pragma unroll
            for (int c = 0; c < 2; c++) {
                int n = nl + c;
                d0[n] = (float)acc[mf][nf][c]     * hs0 * s_zs[n] + s_zb[n];
                d1[n] = (float)acc[mf][nf][c + 2] * hs1 * s_zs[n] + s_zb[n];
            }
        }
    }
}

// ---------------- combine ----------------
__global__ void k_combine(float* __restrict__ out) {
    int tkn = blockIdx.x, t = threadIdx.x;
    int h0 = t * 8;
    float r[8] = {0, 0, 0, 0, 0, 0, 0, 0};
    #pragma unroll
    for (int k = 0; k < K_TOP; k++) {
        int sl = g_slot[tkn * K_TOP + k];
        if (sl >= 0) {
            float w = g_topk_w[tkn * K_TOP + k];
            const float4* zp = (const float4*)&g_z[(size_t)sl * H_DIM + h0];
            float4 z0 = zp[0], z1 = zp[1];
            r[0] += w * z0.x; r[1] += w * z0.y; r[2] += w * z0.z; r[3] += w * z0.w;
            r[4] += w * z1.x; r[5] += w * z1.y; r[6] += w * z1.z; r[7] += w * z1.w;
        }
    }
    float* op = out + (size_t)tkn * H_DIM + h0;
    *(float4*)op       = make_float4(r[0], r[1], r[2], r[3]);
    *(float4*)(op + 4) = make_float4(r[4], r[5], r[6], r[7]);
}

// ---------------- launch ----------------
extern "C" void kernel_launch(void* const* d_in, const int* in_sizes, int n_in,
                              void* d_out, int out_size) {
    const float* hidden = (const float*)d_in[0];
    const float* logits = (const float*)d_in[1];
    const float* w1     = (const float*)d_in[2];
    const float* w1s    = (const float*)d_in[3];
    const float* w1b    = (const float*)d_in[4];
    const float* smooth = (const float*)d_in[5];
    const float* w2     = (const float*)d_in[6];
    const float* w2s    = (const float*)d_in[7];
    const float* w2b    = (const float*)d_in[8];
    float* out = (float*)d_out;

    // repack weights to K-packed int8
    k_pack<<<32768, 256>>>(w1, 0, H_DIM, N1);
    k_pack<<<16384, 256>>>(w2, 1, I_DIM, H_DIM);

    // gating + token quant + routing
    k_gate<<<T_TOK, 32>>>(logits);
    k_quant<<<T_TOK, 256>>>(hidden, 0);
    k_route<<<1, 512>>>();

    // expert MLP on IMMA tensor cores
    k_gemm1<<<dim3(32, 4, E_EXP), 256>>>(w1s, w1b, smooth);
    k_quant<<<E_EXP * CAP, 256>>>(nullptr, 1);
    k_gemm2<<<dim3(16, 4, E_EXP), 256>>>(w2s, w2b);

    // weighted combine
    k_combine<<<T_TOK, 256>>>(out);
}

// round 10
// speedup vs baseline: 1.0126x; 1.0126x over previous
#include <cuda_runtime.h>
#include <math.h>

#define T_TOK 1024
#define E_EXP 16
#define K_TOP 4
#define H_DIM 2048
#define I_DIM 2048
#define CAP   512
#define N1    (2*I_DIM)   /* 4096 */

// ---------------- scratch (device globals; no runtime allocation) ----------------
__device__ int   g_w1p[E_EXP*(H_DIM/4)*N1];     // [E][K/4][2I] int32: byte j = k = 4*k4+j
__device__ int   g_w2p[E_EXP*(I_DIM/4)*H_DIM];  // [E][K/4][H]
__device__ int   g_xq[T_TOK*(H_DIM/4)];         // packed int8 tokens [T][512]
__device__ float g_xs[T_TOK];
__device__ int   g_topk_i[T_TOK*K_TOP];
__device__ float g_topk_w[T_TOK*K_TOP];
__device__ int   g_rowsrc[E_EXP*CAP];
__device__ int   g_slot[T_TOK*K_TOP];
__device__ int   g_cnt[E_EXP];
__device__ float g_act[(size_t)E_EXP*CAP*I_DIM];   // swiglu output
__device__ int   g_hq[E_EXP*CAP*(I_DIM/4)];        // requantized act
__device__ float g_hs[E_EXP*CAP];
__device__ float g_z[(size_t)E_EXP*CAP*H_DIM];     // GEMM2 output

// ---------------- helpers ----------------
__device__ __forceinline__ int packb(float a, float b, float c, float d) {
    return ( __float2int_rn(a) & 0xff)
         | ((__float2int_rn(b) & 0xff) << 8)
         | ((__float2int_rn(c) & 0xff) << 16)
         | ((__float2int_rn(d) & 0xff) << 24);
}
__device__ __forceinline__ int q8c(float v, float s) {
    int q = __float2int_rn(v / s);
    q = max(-127, min(127, q));
    return q & 0xff;
}
// IMMA m16n8k32 s8*s8+s32
__device__ __forceinline__ void mma_s8(int* c, const int* a, const int* b) {
    asm volatile("mma.sync.aligned.m16n8k32.row.col.s32.s8.s8.s32 "
        "{%0,%1,%2,%3}, {%4,%5,%6,%7}, {%8,%9}, {%0,%1,%2,%3};"
        : "+r"(c[0]), "+r"(c[1]), "+r"(c[2]), "+r"(c[3])
        : "r"(a[0]), "r"(a[1]), "r"(a[2]), "r"(a[3]), "r"(b[0]), "r"(b[1]));
}

// ---------------- weight repack: f32 (int values) -> K-packed int8 ----------------
__global__ void k_pack(const float* __restrict__ in, int which, int Kd, int Nd) {
    int* __restrict__ out = which ? g_w2p : g_w1p;
    long long i4  = (long long)blockIdx.x * blockDim.x + threadIdx.x;
    long long lin = i4 * 4;
    long long perE = (long long)(Kd >> 2) * Nd;
    int e  = (int)(lin / perE);
    long long rem = lin - (long long)e * perE;
    int k4 = (int)(rem / Nd);
    int n  = (int)(rem - (long long)k4 * Nd);
    const float* p = in + ((long long)e * Kd + 4 * k4) * Nd + n;
    float4 r0 = *(const float4*)(p);
    float4 r1 = *(const float4*)(p + Nd);
    float4 r2 = *(const float4*)(p + 2 * Nd);
    float4 r3 = *(const float4*)(p + 3 * Nd);
    int4 o;
    o.x = packb(r0.x, r1.x, r2.x, r3.x);
    o.y = packb(r0.y, r1.y, r2.y, r3.y);
    o.z = packb(r0.z, r1.z, r2.z, r3.z);
    o.w = packb(r0.w, r1.w, r2.w, r3.w);
    *(int4*)(out + lin) = o;
}

// ---------------- gating: softmax + top-4 + renormalize ----------------
__global__ void k_gate(const float* __restrict__ logits) {
    int t = blockIdx.x, lane = threadIdx.x;
    float v = (lane < E_EXP) ? logits[t * E_EXP + lane] : -1e30f;
    float m = v;
    #pragma unroll
    for (int o = 16; o; o >>= 1) m = fmaxf(m, __shfl_xor_sync(0xffffffffu, m, o));
    float cur = (lane < E_EXP) ? expf(v - m) : -1.0f;
    float w[K_TOP]; int id[K_TOP];
    #pragma unroll
    for (int k = 0; k < K_TOP; k++) {
        float bv = cur; int bi = lane;
        #pragma unroll
        for (int o = 16; o; o >>= 1) {
            float ov = __shfl_xor_sync(0xffffffffu, bv, o);
            int   oi = __shfl_xor_sync(0xffffffffu, bi, o);
            if (ov > bv || (ov == bv && oi < bi)) { bv = ov; bi = oi; }
        }
        w[k] = bv; id[k] = bi;
        if (lane == bi) cur = -1.0f;
    }
    float s = w[0] + w[1] + w[2] + w[3];
    if (lane < K_TOP) {
        g_topk_i[t * K_TOP + lane] = id[lane];
        g_topk_w[t * K_TOP + lane] = w[lane] / s;
    }
}

// ---------------- per-row dynamic int8 quant ----------------
__global__ void k_quant(const float* __restrict__ xin, int which) {
    const float* x; int* q; float* s;
    if (which == 0) { x = xin;  q = g_xq; s = g_xs; }
    else            { x = g_act; q = g_hq; s = g_hs; }
    int r = blockIdx.x, t = threadIdx.x;
    const float* row = x + (long long)r * 2048;
    float4 a = *(const float4*)(row + t * 8);
    float4 b = *(const float4*)(row + t * 8 + 4);
    float mx = fmaxf(fmaxf(fmaxf(fabsf(a.x), fabsf(a.y)), fmaxf(fabsf(a.z), fabsf(a.w))),
                     fmaxf(fmaxf(fabsf(b.x), fabsf(b.y)), fmaxf(fabsf(b.z), fabsf(b.w))));
    __shared__ float sm[256];
    sm[t] = mx; __syncthreads();
    #pragma unroll
    for (int o = 128; o; o >>= 1) { if (t < o) sm[t] = fmaxf(sm[t], sm[t + o]); __syncthreads(); }
    float scale = fmaxf(sm[0] / 127.0f, 1e-8f);
    int2 o2;
    o2.x = q8c(a.x, scale) | (q8c(a.y, scale) << 8) | (q8c(a.z, scale) << 16) | (q8c(a.w, scale) << 24);
    o2.y = q8c(b.x, scale) | (q8c(b.y, scale) << 8) | (q8c(b.z, scale) << 16) | (q8c(b.w, scale) << 24);
    *(int2*)(q + (long long)r * 512 + t * 2) = o2;
    if (t == 0) s[r] = scale;
}

// ---------------- routing ----------------
__global__ void k_route() {
    int w = threadIdx.x >> 5, lane = threadIdx.x & 31;
    int base = 0;
    for (int c = 0; c < (T_TOK * K_TOP) / 32; c++) {
        int i = c * 32 + lane;
        int e = g_topk_i[i];
        unsigned mask = __ballot_sync(0xffffffffu, e == w);
        if (e == w) {
            int pos = base + __popc(mask & ((1u << lane) - 1u));
            if (pos < CAP) { g_rowsrc[w * CAP + pos] = i >> 2; g_slot[i] = w * CAP + pos; }
            else           { g_slot[i] = -1; }
        }
        base += __popc(mask);
    }
    int cnt = min(base, CAP);
    if (lane == 0) g_cnt[w] = cnt;
    for (int p = cnt + lane; p < CAP; p += 32) g_rowsrc[w * CAP + p] = -1;
}

// ---------------- GEMM1: IMMA m16n8k32, CTA 128m x (64 gate + 64 up), K=2048 ----------------
// grid (32, 4, 16). 8 warps = 4m x 2n; warp tile 32m x 32n (gate) + 32m x 32n (up).
__global__ void __launch_bounds__(256) k_gemm1(const float* __restrict__ w1s,
                                               const float* __restrict__ w1b,
                                               const float* __restrict__ smooth) {
    int e = blockIdx.z, mt = blockIdx.y, ng = blockIdx.x;
    int cnt = g_cnt[e];
    if (mt * 128 >= cnt) return;

    __shared__ int As[2][8 * 136];     // [k4][m], stride 136
    __shared__ int Bs[2][8 * 136];     // [k4][cc 0..127], stride 136 (cc<64 gate, >=64 up)
    __shared__ int s_src[128];
    __shared__ float s_xs[128];
    __shared__ float s_gs[64], s_gb[64], s_us[64], s_ub[64], s_sm[64];

    int t = threadIdx.x;
    if (t < 128) {
        int s = g_rowsrc[e * CAP + mt * 128 + t];
        s_src[t] = s;
        s_xs[t] = (s >= 0) ? g_xs[s] : 0.0f;
    }
    if (t < 64) {
        int n = ng * 64 + t;
        s_gs[t] = w1s[e * N1 + n];
        s_gb[t] = w1b[e * N1 + n];
        s_us[t] = w1s[e * N1 + I_DIM + n];
        s_ub[t] = w1b[e * N1 + I_DIM + n];
        s_sm[t] = smooth[e * I_DIM + n];
    }
    __syncthreads();

    int lane = t & 31, wid = t >> 5;
    int wm = (wid & 3) * 32;           // warp m offset
    int wn = (wid >> 2) * 32;          // warp n offset within 64 gate cols
    int grp = lane >> 2, qid = lane & 3;

    // staging indices
    int am = t >> 1, ajj = (t & 1) * 4;                    // A: 2 threads/row, int4 each
    int bj = t >> 5, bn4 = t & 31;                         // B: warp per k4 row
    int srcm = s_src[am];
    int bcc = bn4 * 4;
    long long bcol = (bcc < 64) ? (long long)(ng * 64 + bcc)
                                : (long long)(I_DIM + ng * 64 + (bcc - 64));
    const int* bptr = g_w1p + (long long)e * 512 * N1 + bcol;
    const int* aptr = (srcm >= 0) ? (g_xq + srcm * 512 + ajj) : (const int*)0;

    int accg[2][4][4], accu[2][4][4];
    #pragma unroll
    for (int i = 0; i < 2; i++)
        #pragma unroll
        for (int j = 0; j < 4; j++)
            #pragma unroll
            for (int k = 0; k < 4; k++) { accg[i][j][k] = 0; accu[i][j][k] = 0; }

    // prologue: stage chunk 0 into buf 0
    {
        int4 av = aptr ? *(const int4*)(aptr) : make_int4(0, 0, 0, 0);
        As[0][(ajj + 0) * 136 + am] = av.x;
        As[0][(ajj + 1) * 136 + am] = av.y;
        As[0][(ajj + 2) * 136 + am] = av.z;
        As[0][(ajj + 3) * 136 + am] = av.w;
        int4 bv = *(const int4*)(bptr + (long long)bj * N1);
        *(int4*)&Bs[0][bj * 136 + bn4 * 4] = bv;
    }
    __syncthreads();

    for (int kt = 0; kt < 64; kt++) {
        int buf = kt & 1;
        if (kt + 1 < 64) {
            int k4b = (kt + 1) * 8;
            int nb = buf ^ 1;
            int4 av = aptr ? *(const int4*)(aptr + k4b) : make_int4(0, 0, 0, 0);
            As[nb][(ajj + 0) * 136 + am] = av.x;
            As[nb][(ajj + 1) * 136 + am] = av.y;
            As[nb][(ajj + 2) * 136 + am] = av.z;
            As[nb][(ajj + 3) * 136 + am] = av.w;
            int4 bv = *(const int4*)(bptr + (long long)(k4b + bj) * N1);
            *(int4*)&Bs[nb][bj * 136 + bn4 * 4] = bv;
        }
        int a[2][4];
        #pragma unroll
        for (int mf = 0; mf < 2; mf++) {
            int mr = wm + mf * 16 + grp;
            a[mf][0] = As[buf][qid * 136 + mr];
            a[mf][1] = As[buf][qid * 136 + mr + 8];
            a[mf][2] = As[buf][(qid + 4) * 136 + mr];
            a[mf][3] = As[buf][(qid + 4) * 136 + mr + 8];
        }
        #pragma unroll
        for (int nf = 0; nf < 4; nf++) {
            int cc = wn + nf * 8 + grp;
            int bg[2] = { Bs[buf][qid * 136 + cc], Bs[buf][(qid + 4) * 136 + cc] };
            int bu[2] = { Bs[buf][qid * 136 + 64 + cc], Bs[buf][(qid + 4) * 136 + 64 + cc] };
            #pragma unroll
            for (int mf = 0; mf < 2; mf++) {
                mma_s8(accg[mf][nf], a[mf], bg);
                mma_s8(accu[mf][nf], a[mf], bu);
            }
        }
        __syncthreads();
    }

    // epilogue: dequant + swiglu, write g_act (cols ng*64 .. +64)
    #pragma unroll
    for (int mf = 0; mf < 2; mf++) {
        int r0 = wm + mf * 16 + grp;
        int r1 = r0 + 8;
        float xs0 = s_xs[r0], xs1 = s_xs[r1];
        float* d0 = g_act + ((size_t)e * CAP + mt * 128 + r0) * I_DIM + (size_t)ng * 64;
        float* d1 = g_act + ((size_t)e * CAP + mt * 128 + r1) * I_DIM + (size_t)ng * 64;
        #pragma unroll
        for (int nf = 0; nf < 4; nf++) {
            int nl = wn + nf * 8 + qid * 2;
            #pragma unroll
            for (int c = 0; c < 2; c++) {
                int n = nl + c;
                float gs = s_gs[n], gbv = s_gb[n], us = s_us[n], ubv = s_ub[n], smv = s_sm[n];
                // row r0: acc idx c, row r1: acc idx c+2
                float yg0 = (float)accg[mf][nf][c]     * xs0 * gs + gbv;
                float yu0 = (float)accu[mf][nf][c]     * xs0 * us + ubv;
                float yg1 = (float)accg[mf][nf][c + 2] * xs1 * gs + gbv;
                float yu1 = (float)accu[mf][nf][c + 2] * xs1 * us + ubv;
                float gg0 = fminf(yg0, 7.0f), uu0 = fminf(fmaxf(yu0, -7.0f), 7.0f);
                float gg1 = fminf(yg1, 7.0f), uu1 = fminf(fmaxf(yu1, -7.0f), 7.0f);
                d0[n] = gg0 / (1.0f + expf(-1.702f * gg0)) * (uu0 + 1.0f) * smv;
                d1[n] = gg1 / (1.0f + expf(-1.702f * gg1)) * (uu1 + 1.0f) * smv;
            }
        }
    }
}

// ---------------- GEMM2: IMMA m16n8k32, CTA 128m x 128n, K=2048 ----------------
// grid (16, 4, 16). 8 warps = 4m x 2n; warp tile 32m x 64n.
__global__ void __launch_bounds__(256) k_gemm2(const float* __restrict__ w2s,
                                               const float* __restrict__ w2b) {
    int e = blockIdx.z, mt = blockIdx.y, nt = blockIdx.x;
    int cnt = g_cnt[e];
    if (mt * 128 >= cnt) return;

    __shared__ int As[2][8 * 136];
    __shared__ int Bs[2][8 * 136];
    __shared__ float s_hs[128];
    __shared__ float s_zs[128], s_zb[128];

    int t = threadIdx.x;
    if (t < 128) {
        s_hs[t] = g_hs[e * CAP + mt * 128 + t];
        int n = nt * 128 + t;
        s_zs[t] = w2s[e * H_DIM + n];
        s_zb[t] = w2b[e * H_DIM + n];
    }
    __syncthreads();

    int lane = t & 31, wid = t >> 5;
    int wm = (wid & 3) * 32;
    int wn = (wid >> 2) * 64;
    int grp = lane >> 2, qid = lane & 3;

    int am = t >> 1, ajj = (t & 1) * 4;
    int bj = t >> 5, bn4 = t & 31;
    const int* aptr = g_hq + ((long long)e * CAP + mt * 128 + am) * 512 + ajj;
    const int* bptr = g_w2p + (long long)e * 512 * H_DIM + nt * 128 + bn4 * 4;

    int acc[2][8][4];
    #pragma unroll
    for (int i = 0; i < 2; i++)
        #pragma unroll
        for (int j = 0; j < 8; j++)
            #pragma unroll
            for (int k = 0; k < 4; k++) acc[i][j][k] = 0;

    {
        int4 av = *(const int4*)(aptr);
        As[0][(ajj + 0) * 136 + am] = av.x;
        As[0][(ajj + 1) * 136 + am] = av.y;
        As[0][(ajj + 2) * 136 + am] = av.z;
        As[0][(ajj + 3) * 136 + am] = av.w;
        int4 bv = *(const int4*)(bptr + (long long)bj * H_DIM);
        *(int4*)&Bs[0][bj * 136 + bn4 * 4] = bv;
    }
    __syncthreads();

    for (int kt = 0; kt < 64; kt++) {
        int buf = kt & 1;
        if (kt + 1 < 64) {
            int k4b = (kt + 1) * 8;
            int nb = buf ^ 1;
            int4 av = *(const int4*)(aptr + k4b);
            As[nb][(ajj + 0) * 136 + am] = av.x;
            As[nb][(ajj + 1) * 136 + am] = av.y;
            As[nb][(ajj + 2) * 136 + am] = av.z;
            As[nb][(ajj + 3) * 136 + am] = av.w;
            int4 bv = *(const int4*)(bptr + (long long)(k4b + bj) * H_DIM);
            *(int4*)&Bs[nb][bj * 136 + bn4 * 4] = bv;
        }
        int a[2][4];
        #pragma unroll
        for (int mf = 0; mf < 2; mf++) {
            int mr = wm + mf * 16 + grp;
            a[mf][0] = As[buf][qid * 136 + mr];
            a[mf][1] = As[buf][qid * 136 + mr + 8];
            a[mf][2] = As[buf][(qid + 4) * 136 + mr];
            a[mf][3] = As[buf][(qid + 4) * 136 + mr + 8];
        }
        #pragma unroll
        for (int nf = 0; nf < 8; nf++) {
            int cc = wn + nf * 8 + grp;
            int b[2] = { Bs[buf][qid * 136 + cc], Bs[buf][(qid + 4) * 136 + cc] };
            #pragma unroll
            for (int mf = 0; mf < 2; mf++)
                mma_s8(acc[mf][nf], a[mf], b);
        }
        __syncthreads();
    }

    #pragma unroll
    for (int mf = 0; mf < 2; mf++) {
        int r0 = wm + mf * 16 + grp;
        int r1 = r0 + 8;
        float hs0 = s_hs[r0], hs1 = s_hs[r1];
        float* d0 = g_z + ((size_t)e * CAP + mt * 128 + r0) * H_DIM + (size_t)nt * 128;
        float* d1 = g_z + ((size_t)e * CAP + mt * 128 + r1) * H_DIM + (size_t)nt * 128;
        #pragma unroll
        for (int nf = 0; nf < 8; nf++) {
            int nl = wn + nf * 8 + qid * 2;
            #pragma unroll
            for (int c = 0; c < 2; c++) {
                int n = nl + c;
                d0[n] = (float)acc[mf][nf][c]     * hs0 * s_zs[n] + s_zb[n];
                d1[n] = (float)acc[mf][nf][c + 2] * hs1 * s_zs[n] + s_zb[n];
            }
        }
    }
}

// ---------------- combine ----------------
__global__ void k_combine(float* __restrict__ out) {
    int tkn = blockIdx.x, t = threadIdx.x;
    int h0 = t * 8;
    float r[8] = {0, 0, 0, 0, 0, 0, 0, 0};
    #pragma unroll
    for (int k = 0; k < K_TOP; k++) {
        int sl = g_slot[tkn * K_TOP + k];
        if (sl >= 0) {
            float w = g_topk_w[tkn * K_TOP + k];
            const float4* zp = (const float4*)&g_z[(size_t)sl * H_DIM + h0];
            float4 z0 = zp[0], z1 = zp[1];
            r[0] += w * z0.x; r[1] += w * z0.y; r[2] += w * z0.z; r[3] += w * z0.w;
            r[4] += w * z1.x; r[5] += w * z1.y; r[6] += w * z1.z; r[7] += w * z1.w;
        }
    }
    float* op = out + (size_t)tkn * H_DIM + h0;
    *(float4*)op       = make_float4(r[0], r[1], r[2], r[3]);
    *(float4*)(op + 4) = make_float4(r[4], r[5], r[6], r[7]);
}

// ---------------- launch ----------------
extern "C" void kernel_launch(void* const* d_in, const int* in_sizes, int n_in,
                              void* d_out, int out_size) {
    const float* hidden = (const float*)d_in[0];
    const float* logits = (const float*)d_in[1];
    const float* w1     = (const float*)d_in[2];
    const float* w1s    = (const float*)d_in[3];
    const float* w1b    = (const float*)d_in[4];
    const float* smooth = (const float*)d_in[5];
    const float* w2     = (const float*)d_in[6];
    const float* w2s    = (const float*)d_in[7];
    const float* w2b    = (const float*)d_in[8];
    float* out = (float*)d_out;

    // repack weights to K-packed int8
    k_pack<<<32768, 256>>>(w1, 0, H_DIM, N1);
    k_pack<<<16384, 256>>>(w2, 1, I_DIM, H_DIM);

    // gating + token quant + routing
    k_gate<<<T_TOK, 32>>>(logits);
    k_quant<<<T_TOK, 256>>>(hidden, 0);
    k_route<<<1, 512>>>();

    // expert MLP on IMMA tensor cores
    k_gemm1<<<dim3(32, 4, E_EXP), 256>>>(w1s, w1b, smooth);
    k_quant<<<E_EXP * CAP, 256>>>(nullptr, 1);
    k_gemm2<<<dim3(16, 4, E_EXP), 256>>>(w2s, w2b);

    // weighted combine
    k_combine<<<T_TOK, 256>>>(out);
}